// round 16
// baseline (speedup 1.0000x reference)
#include <cuda_runtime.h>
#include <math.h>

#define B_TOTAL 32768
#define NM 6
#define T 30
#define TPB 512
#define WARPS 16
#define AB 256                     // agents per block (16 per warp)
#define NBLK (B_TOTAL / AB)        // 128 -> single wave

// smem u32 offsets (uint4-aligned where needed)
#define OFF_GB 0                   // gate B frags: 160 frags * 32 lanes * uint4 = 20480 u32
#define OFF_PB 20480               // Wpos: 8 frags  -> 1024 u32
#define OFF_SB 21504               // Wse:  2 frags  -> 256 u32
#define OFF_CB 21760               // Wconf:4 frags  -> 512 u32
#define OFF_BG 22272               // 256 floats
#define OFF_BP 22528               // 16
#define OFF_BS 22544               // 16
#define OFF_BC 22560               // 8
#define OFF_CS 22568               // c state: 512 threads * 33 floats = 16896
#define CST 33                     // per-thread stride -> conflict-free scalar access
#define OFF_HN (OFF_CS + TPB * CST)          // 39464; h_new lane-private slots
#define HNST 36                    // u32 stride/thread (9 uint4) -> conflict-free LDS.128
#define SMEM_U32 (OFF_HN + TPB * HNST)       // 57896
#define SMEM_BYTES (SMEM_U32 * 4)            // 231584 B (<= 232448 cap)

#define CONF_BASE ((size_t)B_TOTAL * NM * T * 2)

__device__ __forceinline__ void stage_pair(float f0, float f1, unsigned& H, unsigned& L) {
    asm("cvt.rn.bf16x2.f32 %0, %1, %2;" : "=r"(H) : "f"(f1), "f"(f0));  // low=f0, high=f1
    float r0 = f0 - __uint_as_float(H << 16);
    float r1 = f1 - __uint_as_float(H & 0xFFFF0000u);
    asm("cvt.rn.bf16x2.f32 %0, %1, %2;" : "=r"(L) : "f"(r1), "f"(r0));
}
__device__ __forceinline__ void mmab(float* d, const unsigned* a, unsigned b0, unsigned b1) {
    asm("mma.sync.aligned.m16n8k16.row.col.f32.bf16.bf16.f32 "
        "{%0,%1,%2,%3},{%4,%5,%6,%7},{%8,%9},{%0,%1,%2,%3};"
        : "+f"(d[0]), "+f"(d[1]), "+f"(d[2]), "+f"(d[3])
        : "r"(a[0]), "r"(a[1]), "r"(a[2]), "r"(a[3]), "r"(b0), "r"(b1));
}
__device__ __forceinline__ float frcp_(float x) {
    float r; asm("rcp.approx.f32 %0, %1;" : "=f"(r) : "f"(x)); return r;
}
__device__ __forceinline__ float tanh_(float v) {
    float r; asm("tanh.approx.f32 %0, %1;" : "=f"(r) : "f"(v)); return r;
}
__device__ __forceinline__ float fsig(float v) { return fmaf(0.5f, tanh_(0.5f * v), 0.5f); }

__global__ void __launch_bounds__(TPB, 1)
decoder_lstm_kernel(const float* __restrict__ traj_rel,
                    const float* __restrict__ h0,
                    const float* __restrict__ c0,
                    const float* __restrict__ W_ih,
                    const float* __restrict__ W_hh,
                    const float* __restrict__ b_ih,
                    const float* __restrict__ b_hh,
                    const float* __restrict__ W_se,
                    const float* __restrict__ b_se,
                    const float* __restrict__ W_pos,
                    const float* __restrict__ b_pos,
                    const float* __restrict__ W_conf,
                    const float* __restrict__ b_conf,
                    float* __restrict__ out)
{
    extern __shared__ float smf[];
    unsigned* smu = (unsigned*)smf;
    uint4* gB4 = (uint4*)(smu + OFF_GB);
    uint4* pB4 = (uint4*)(smu + OFF_PB);
    uint4* sB4 = (uint4*)(smu + OFF_SB);
    uint4* cB4 = (uint4*)(smu + OFF_CB);
    const int tid = threadIdx.x;

    // ---- stage gate weights: frag = ch*32 + ntile; uint4 {H0,H1,L0,L1} per lane ----
    for (int idx = tid; idx < 160 * 32; idx += TPB) {
        int frag = idx >> 5, lane = idx & 31;
        int ch = frag >> 5, ntile = frag & 31;
        int g = lane >> 2, q = lane & 3;
        int n = ntile * 8 + g;
        int k0 = ch * 16 + 2 * q, k1 = k0 + 8;
        float v00 = (k0 < 64) ? W_hh[n * 64 + k0] : W_ih[n * 16 + (k0 - 64)];
        float v01 = (k0 + 1 < 64) ? W_hh[n * 64 + k0 + 1] : W_ih[n * 16 + (k0 + 1 - 64)];
        float v10 = (k1 < 64) ? W_hh[n * 64 + k1] : W_ih[n * 16 + (k1 - 64)];
        float v11 = (k1 + 1 < 64) ? W_hh[n * 64 + k1 + 1] : W_ih[n * 16 + (k1 + 1 - 64)];
        unsigned H0, L0, H1, L1;
        stage_pair(v00, v01, H0, L0);
        stage_pair(v10, v11, H1, L1);
        gB4[idx] = make_uint4(H0, H1, L0, L1);
    }
    // Wpos: frag = ch*2 + nt (ch 0..3); p = nt*8+g (valid < 12)
    for (int idx = tid; idx < 8 * 32; idx += TPB) {
        int frag = idx >> 5, lane = idx & 31;
        int ch = frag >> 1, nt = frag & 1;
        int g = lane >> 2, q = lane & 3;
        int p = nt * 8 + g;
        int k0 = ch * 16 + 2 * q, k1 = k0 + 8;
        float v00 = (p < 12) ? W_pos[p * 64 + k0] : 0.f;
        float v01 = (p < 12) ? W_pos[p * 64 + k0 + 1] : 0.f;
        float v10 = (p < 12) ? W_pos[p * 64 + k1] : 0.f;
        float v11 = (p < 12) ? W_pos[p * 64 + k1 + 1] : 0.f;
        unsigned H0, L0, H1, L1;
        stage_pair(v00, v01, H0, L0);
        stage_pair(v10, v11, H1, L1);
        pB4[idx] = make_uint4(H0, H1, L0, L1);
    }
    // Wse: frag = nt (0..1); e = nt*8+g; K=16 (valid k<12)
    for (int idx = tid; idx < 2 * 32; idx += TPB) {
        int frag = idx >> 5, lane = idx & 31;
        int g = lane >> 2, q = lane & 3;
        int e = frag * 8 + g;
        int k0 = 2 * q, k1 = k0 + 8;
        float v00 = (k0 < 12) ? W_se[e * 12 + k0] : 0.f;
        float v01 = (k0 + 1 < 12) ? W_se[e * 12 + k0 + 1] : 0.f;
        float v10 = (k1 < 12) ? W_se[e * 12 + k1] : 0.f;
        float v11 = (k1 + 1 < 12) ? W_se[e * 12 + k1 + 1] : 0.f;
        unsigned H0, L0, H1, L1;
        stage_pair(v00, v01, H0, L0);
        stage_pair(v10, v11, H1, L1);
        sB4[idx] = make_uint4(H0, H1, L0, L1);
    }
    // Wconf: frag = ch (0..3); m = g (valid < 6)
    for (int idx = tid; idx < 4 * 32; idx += TPB) {
        int frag = idx >> 5, lane = idx & 31;
        int g = lane >> 2, q = lane & 3;
        int k0 = frag * 16 + 2 * q, k1 = k0 + 8;
        float v00 = (g < 6) ? W_conf[g * 64 + k0] : 0.f;
        float v01 = (g < 6) ? W_conf[g * 64 + k0 + 1] : 0.f;
        float v10 = (g < 6) ? W_conf[g * 64 + k1] : 0.f;
        float v11 = (g < 6) ? W_conf[g * 64 + k1 + 1] : 0.f;
        unsigned H0, L0, H1, L1;
        stage_pair(v00, v01, H0, L0);
        stage_pair(v10, v11, H1, L1);
        cB4[idx] = make_uint4(H0, H1, L0, L1);
    }
    if (tid < 256) smf[OFF_BG + tid] = b_ih[tid] + b_hh[tid];
    if (tid < 16)  smf[OFF_BP + tid] = (tid < 12) ? b_pos[tid] : 0.f;
    if (tid < 16)  smf[OFF_BS + tid] = b_se[tid];
    if (tid < 8)   smf[OFF_BC + tid] = (tid < 6) ? b_conf[tid] : 0.f;

    const int l = tid & 31, g = l >> 2, q = l & 3;
    const int ag0 = blockIdx.x * AB + (tid >> 5) * 16;
    const int rowg = ag0 + g, rowg8 = ag0 + g + 8;
    float* cs = smf + OFF_CS + tid * CST;                    // 32 c-values, conflict-free
    uint4* hn4 = (uint4*)(smu + OFF_HN + tid * HNST);        // 8 lane-private h_new slots

    // ---- c state into SMEM (D layout) ----
    #pragma unroll
    for (int grp = 0; grp < 8; grp++) {
        cs[grp * 4 + 0] = c0[(size_t)rowg  * 64 + grp * 8 + 2 * q];
        cs[grp * 4 + 1] = c0[(size_t)rowg  * 64 + grp * 8 + 2 * q + 1];
        cs[grp * 4 + 2] = c0[(size_t)rowg8 * 64 + grp * 8 + 2 * q];
        cs[grp * 4 + 3] = c0[(size_t)rowg8 * 64 + grp * 8 + 2 * q + 1];
    }
    __syncthreads();

    // ---- register-resident A fragments: chunks 0..3 = h, chunk 4 = x ----
    unsigned Ah[5][4], Al[5][4];
    {
        const float* hg  = h0 + (size_t)rowg * 64;
        const float* hg8 = h0 + (size_t)rowg8 * 64;
        #pragma unroll
        for (int ch = 0; ch < 4; ch++) {
            float2 v;
            v = *(const float2*)(hg  + ch * 16 + 2 * q);     stage_pair(v.x, v.y, Ah[ch][0], Al[ch][0]);
            v = *(const float2*)(hg8 + ch * 16 + 2 * q);     stage_pair(v.x, v.y, Ah[ch][1], Al[ch][1]);
            v = *(const float2*)(hg  + ch * 16 + 8 + 2 * q); stage_pair(v.x, v.y, Ah[ch][2], Al[ch][2]);
            v = *(const float2*)(hg8 + ch * 16 + 8 + 2 * q); stage_pair(v.x, v.y, Ah[ch][3], Al[ch][3]);
        }
        // x init per lane: rows g and g+8, e in {2q,2q+1} and {8+2q,8+2q+1}
        float xa[2][4];
        #pragma unroll
        for (int rr = 0; rr < 2; rr++) {
            int agent = rr ? rowg8 : rowg;
            float rx = traj_rel[2 * agent], ry = traj_rel[2 * agent + 1];
            #pragma unroll
            for (int u = 0; u < 4; u++) {
                int e = (u < 2) ? (2 * q + u) : (8 + 2 * q + (u - 2));
                float se = 0.f, so = 0.f;
                #pragma unroll
                for (int p = 0; p < 6; p++) { se += W_se[e * 12 + 2 * p]; so += W_se[e * 12 + 2 * p + 1]; }
                float s = b_se[e] + rx * se + ry * so;
                xa[rr][u] = s > 0.f ? s : 0.01f * s;
            }
        }
        stage_pair(xa[0][0], xa[0][1], Ah[4][0], Al[4][0]);
        stage_pair(xa[1][0], xa[1][1], Ah[4][1], Al[4][1]);
        stage_pair(xa[0][2], xa[0][3], Ah[4][2], Al[4][2]);
        stage_pair(xa[1][2], xa[1][3], Ah[4][3], Al[4][3]);
    }

    float* outA = out + (size_t)rowg  * 360;
    float* outB = out + (size_t)rowg8 * 360;

    #pragma unroll 1
    for (int t = 0; t < T; t++) {
        // ---- gates: 8 groups of 8 cells; h_new -> lane-private SMEM slots ----
        #pragma unroll
        for (int grp = 0; grp < 8; grp++) {
            float acc[4][4];
            #pragma unroll
            for (int gate = 0; gate < 4; gate++) {
                float2 bb = *(const float2*)(smf + OFF_BG + gate * 64 + grp * 8 + 2 * q);
                acc[gate][0] = bb.x; acc[gate][1] = bb.y;
                acc[gate][2] = bb.x; acc[gate][3] = bb.y;
            }
            #pragma unroll
            for (int ch = 0; ch < 5; ch++) {
                #pragma unroll
                for (int gate = 0; gate < 4; gate++) {
                    uint4 B = gB4[(ch * 32 + gate * 8 + grp) * 32 + l];
                    mmab(acc[gate], Ah[ch], B.x, B.y);
                    mmab(acc[gate], Al[ch], B.x, B.y);
                    mmab(acc[gate], Ah[ch], B.z, B.w);
                }
            }
            float hv[4];
            #pragma unroll
            for (int j = 0; j < 4; j++) {
                float cc = fsig(acc[1][j]) * cs[grp * 4 + j] + fsig(acc[0][j]) * tanh_(acc[2][j]);
                cs[grp * 4 + j] = cc;
                hv[j] = fsig(acc[3][j]) * tanh_(cc);
            }
            unsigned H0, L0, H1, L1;
            stage_pair(hv[0], hv[1], H0, L0);   // row g
            stage_pair(hv[2], hv[3], H1, L1);   // row g+8
            hn4[grp] = make_uint4(H0, H1, L0, L1);   // lane-private; program order suffices
        }
        // commit h_new -> A chunks 0..3 (lane-local SMEM reload, no sync)
        #pragma unroll
        for (int ch = 0; ch < 4; ch++) {
            uint4 a = hn4[2 * ch], b = hn4[2 * ch + 1];
            Ah[ch][0] = a.x; Ah[ch][1] = a.y; Ah[ch][2] = b.x; Ah[ch][3] = b.y;
            Al[ch][0] = a.z; Al[ch][1] = a.w; Al[ch][2] = b.z; Al[ch][3] = b.w;
        }

        // ---- rel = h_new @ Wpos^T + bpos ----
        float ar[2][4];
        {
            float2 b0 = *(const float2*)(smf + OFF_BP + 2 * q);
            float2 b1 = *(const float2*)(smf + OFF_BP + 8 + 2 * q);
            ar[0][0] = b0.x; ar[0][1] = b0.y; ar[0][2] = b0.x; ar[0][3] = b0.y;
            ar[1][0] = b1.x; ar[1][1] = b1.y; ar[1][2] = b1.x; ar[1][3] = b1.y;
        }
        #pragma unroll
        for (int ch = 0; ch < 4; ch++) {
            #pragma unroll
            for (int nt = 0; nt < 2; nt++) {
                uint4 B = pB4[(ch * 2 + nt) * 32 + l];
                mmab(ar[nt], Ah[ch], B.x, B.y);
                mmab(ar[nt], Al[ch], B.x, B.y);
                mmab(ar[nt], Ah[ch], B.z, B.w);
            }
        }
        *(float2*)(outA + q * 60 + t * 2) = make_float2(ar[0][0], ar[0][1]);
        *(float2*)(outB + q * 60 + t * 2) = make_float2(ar[0][2], ar[0][3]);
        if (q < 2) {
            *(float2*)(outA + (4 + q) * 60 + t * 2) = make_float2(ar[1][0], ar[1][1]);
            *(float2*)(outB + (4 + q) * 60 + t * 2) = make_float2(ar[1][2], ar[1][3]);
        }
        // rel as A fragment for the x GEMM (B rows >= 12 staged as 0)
        unsigned rH[4], rL[4];
        stage_pair(ar[0][0], ar[0][1], rH[0], rL[0]);
        stage_pair(ar[0][2], ar[0][3], rH[1], rL[1]);
        stage_pair(ar[1][0], ar[1][1], rH[2], rL[2]);
        stage_pair(ar[1][2], ar[1][3], rH[3], rL[3]);

        // ---- x = lrelu(rel @ Wse^T + bse) -> A chunk 4 ----
        float ax[2][4];
        {
            float2 b0 = *(const float2*)(smf + OFF_BS + 2 * q);
            float2 b1 = *(const float2*)(smf + OFF_BS + 8 + 2 * q);
            ax[0][0] = b0.x; ax[0][1] = b0.y; ax[0][2] = b0.x; ax[0][3] = b0.y;
            ax[1][0] = b1.x; ax[1][1] = b1.y; ax[1][2] = b1.x; ax[1][3] = b1.y;
        }
        #pragma unroll
        for (int nt = 0; nt < 2; nt++) {
            uint4 B = sB4[nt * 32 + l];
            mmab(ax[nt], rH, B.x, B.y);
            mmab(ax[nt], rL, B.x, B.y);
            mmab(ax[nt], rH, B.z, B.w);
        }
        #pragma unroll
        for (int nt = 0; nt < 2; nt++)
            #pragma unroll
            for (int j = 0; j < 4; j++)
                ax[nt][j] = ax[nt][j] > 0.f ? ax[nt][j] : 0.01f * ax[nt][j];
        stage_pair(ax[0][0], ax[0][1], Ah[4][0], Al[4][0]);
        stage_pair(ax[0][2], ax[0][3], Ah[4][1], Al[4][1]);
        stage_pair(ax[1][0], ax[1][1], Ah[4][2], Al[4][2]);
        stage_pair(ax[1][2], ax[1][3], Ah[4][3], Al[4][3]);
    }

    // ---- confidence head: softmax(h @ Wconf^T + bconf) ----
    float ac[4];
    {
        float2 bc = *(const float2*)(smf + OFF_BC + 2 * q);
        ac[0] = bc.x; ac[1] = bc.y; ac[2] = bc.x; ac[3] = bc.y;
    }
    #pragma unroll
    for (int ch = 0; ch < 4; ch++) {
        uint4 B = cB4[ch * 32 + l];
        mmab(ac, Ah[ch], B.x, B.y);
        mmab(ac, Al[ch], B.x, B.y);
        mmab(ac, Ah[ch], B.z, B.w);
    }
    {
        bool v0 = (2 * q) < 6, v1 = (2 * q + 1) < 6;
        float la = fmaxf(v0 ? ac[0] : -1e30f, v1 ? ac[1] : -1e30f);
        float lb = fmaxf(v0 ? ac[2] : -1e30f, v1 ? ac[3] : -1e30f);
        la = fmaxf(la, __shfl_xor_sync(0xffffffffu, la, 1));
        la = fmaxf(la, __shfl_xor_sync(0xffffffffu, la, 2));
        lb = fmaxf(lb, __shfl_xor_sync(0xffffffffu, lb, 1));
        lb = fmaxf(lb, __shfl_xor_sync(0xffffffffu, lb, 2));
        float ea0 = v0 ? __expf(ac[0] - la) : 0.f, ea1 = v1 ? __expf(ac[1] - la) : 0.f;
        float eb0 = v0 ? __expf(ac[2] - lb) : 0.f, eb1 = v1 ? __expf(ac[3] - lb) : 0.f;
        float sa = ea0 + ea1, sb = eb0 + eb1;
        sa += __shfl_xor_sync(0xffffffffu, sa, 1); sa += __shfl_xor_sync(0xffffffffu, sa, 2);
        sb += __shfl_xor_sync(0xffffffffu, sb, 1); sb += __shfl_xor_sync(0xffffffffu, sb, 2);
        float ra = frcp_(sa), rb = frcp_(sb);
        if (q < 3) {
            float* cA = out + CONF_BASE + (size_t)rowg  * NM + 2 * q;
            float* cB = out + CONF_BASE + (size_t)rowg8 * NM + 2 * q;
            *(float2*)cA = make_float2(ea0 * ra, ea1 * ra);
            *(float2*)cB = make_float2(eb0 * rb, eb1 * rb);
        }
    }
}

extern "C" void kernel_launch(void* const* d_in, const int* in_sizes, int n_in,
                              void* d_out, int out_size)
{
    // 0 traj_abs (unused), 1 traj_rel, 2 h0, 3 c0, 4 W_ih, 5 W_hh,
    // 6 b_ih, 7 b_hh, 8 W_se, 9 b_se, 10 W_pos, 11 b_pos, 12 W_conf, 13 b_conf
    const float* traj_rel = (const float*)d_in[1];
    const float* h0       = (const float*)d_in[2];
    const float* c0       = (const float*)d_in[3];
    const float* W_ih     = (const float*)d_in[4];
    const float* W_hh     = (const float*)d_in[5];
    const float* b_ih     = (const float*)d_in[6];
    const float* b_hh     = (const float*)d_in[7];
    const float* W_se     = (const float*)d_in[8];
    const float* b_se     = (const float*)d_in[9];
    const float* W_pos    = (const float*)d_in[10];
    const float* b_pos    = (const float*)d_in[11];
    const float* W_conf   = (const float*)d_in[12];
    const float* b_conf   = (const float*)d_in[13];
    float* out = (float*)d_out;

    (void)cudaFuncSetAttribute(decoder_lstm_kernel,
                               cudaFuncAttributeMaxDynamicSharedMemorySize,
                               SMEM_BYTES);

    decoder_lstm_kernel<<<NBLK, TPB, SMEM_BYTES>>>(
        traj_rel, h0, c0, W_ih, W_hh, b_ih, b_hh,
        W_se, b_se, W_pos, b_pos, W_conf, b_conf, out);
}

// round 17
// speedup vs baseline: 3.4194x; 3.4194x over previous
#include <cuda_runtime.h>
#include <math.h>

#define B_TOTAL 32768
#define NM 6
#define T 30
#define TPB 256
#define WARPS 8
#define AB 256                     // agents per block (32 per warp, 2 m16 tiles)
#define NBLK (B_TOTAL / AB)        // 128 -> single wave

// smem u32 offsets
#define OFF_GB 0                   // gate B frags: 160 frags * 32 lanes * uint4 = 20480 u32
#define OFF_PB 20480               // Wpos: 8 frags  -> 1024 u32
#define OFF_SB 21504               // Wse:  2 frags  -> 256 u32
#define OFF_CB 21760               // Wconf:4 frags  -> 512 u32
#define OFF_BG 22272               // 256 floats
#define OFF_BP 22528               // 16
#define OFF_BS 22544               // 16
#define OFF_BC 22560               // 8
#define OFF_CS 22568               // c state: 256 thr * 65 floats (64 used)
#define CST 65                     // stride 65 -> conflict-free scalar LDS
#define OFF_HN (OFF_CS + TPB * CST)          // 39208
#define HNST 68                    // u32 stride (17 uint4) -> conflict-free LDS.128
#define SMEM_U32 (OFF_HN + TPB * HNST)       // 56616
#define SMEM_BYTES (SMEM_U32 * 4)            // 226464 B (<= 232448 cap)

#define CONF_BASE ((size_t)B_TOTAL * NM * T * 2)

__device__ __forceinline__ void stage_pair(float f0, float f1, unsigned& H, unsigned& L) {
    asm("cvt.rn.bf16x2.f32 %0, %1, %2;" : "=r"(H) : "f"(f1), "f"(f0));  // low=f0, high=f1
    float r0 = f0 - __uint_as_float(H << 16);
    float r1 = f1 - __uint_as_float(H & 0xFFFF0000u);
    asm("cvt.rn.bf16x2.f32 %0, %1, %2;" : "=r"(L) : "f"(r1), "f"(r0));
}
__device__ __forceinline__ void mmab(float* d, const unsigned* a, unsigned b0, unsigned b1) {
    asm("mma.sync.aligned.m16n8k16.row.col.f32.bf16.bf16.f32 "
        "{%0,%1,%2,%3},{%4,%5,%6,%7},{%8,%9},{%0,%1,%2,%3};"
        : "+f"(d[0]), "+f"(d[1]), "+f"(d[2]), "+f"(d[3])
        : "r"(a[0]), "r"(a[1]), "r"(a[2]), "r"(a[3]), "r"(b0), "r"(b1));
}
__device__ __forceinline__ float frcp_(float x) {
    float r; asm("rcp.approx.f32 %0, %1;" : "=f"(r) : "f"(x)); return r;
}
__device__ __forceinline__ float tanh_(float v) {
    float r; asm("tanh.approx.f32 %0, %1;" : "=f"(r) : "f"(v)); return r;
}
__device__ __forceinline__ float fsig(float v) { return fmaf(0.5f, tanh_(0.5f * v), 0.5f); }

__global__ void __launch_bounds__(TPB, 1)
decoder_lstm_kernel(const float* __restrict__ traj_rel,
                    const float* __restrict__ h0,
                    const float* __restrict__ c0,
                    const float* __restrict__ W_ih,
                    const float* __restrict__ W_hh,
                    const float* __restrict__ b_ih,
                    const float* __restrict__ b_hh,
                    const float* __restrict__ W_se,
                    const float* __restrict__ b_se,
                    const float* __restrict__ W_pos,
                    const float* __restrict__ b_pos,
                    const float* __restrict__ W_conf,
                    const float* __restrict__ b_conf,
                    float* __restrict__ out)
{
    extern __shared__ float smf[];
    unsigned* smu = (unsigned*)smf;
    uint4* gB4 = (uint4*)(smu + OFF_GB);
    uint4* pB4 = (uint4*)(smu + OFF_PB);
    uint4* sB4 = (uint4*)(smu + OFF_SB);
    uint4* cB4 = (uint4*)(smu + OFF_CB);
    const int tid = threadIdx.x;

    // ---- stage gate weights: frag = ch*32 + ntile; uint4 {H0,H1,L0,L1} per lane ----
    for (int idx = tid; idx < 160 * 32; idx += TPB) {
        int frag = idx >> 5, lane = idx & 31;
        int ch = frag >> 5, ntile = frag & 31;
        int gg = lane >> 2, qq = lane & 3;
        int n = ntile * 8 + gg;
        int k0 = ch * 16 + 2 * qq, k1 = k0 + 8;
        float v00 = (k0 < 64) ? W_hh[n * 64 + k0] : W_ih[n * 16 + (k0 - 64)];
        float v01 = (k0 + 1 < 64) ? W_hh[n * 64 + k0 + 1] : W_ih[n * 16 + (k0 + 1 - 64)];
        float v10 = (k1 < 64) ? W_hh[n * 64 + k1] : W_ih[n * 16 + (k1 - 64)];
        float v11 = (k1 + 1 < 64) ? W_hh[n * 64 + k1 + 1] : W_ih[n * 16 + (k1 + 1 - 64)];
        unsigned H0, L0, H1, L1;
        stage_pair(v00, v01, H0, L0);
        stage_pair(v10, v11, H1, L1);
        gB4[idx] = make_uint4(H0, H1, L0, L1);
    }
    // Wpos: frag = ch*2 + nt (ch 0..3); p = nt*8+g (valid < 12)
    for (int idx = tid; idx < 8 * 32; idx += TPB) {
        int frag = idx >> 5, lane = idx & 31;
        int ch = frag >> 1, nt = frag & 1;
        int gg = lane >> 2, qq = lane & 3;
        int p = nt * 8 + gg;
        int k0 = ch * 16 + 2 * qq, k1 = k0 + 8;
        float v00 = (p < 12) ? W_pos[p * 64 + k0] : 0.f;
        float v01 = (p < 12) ? W_pos[p * 64 + k0 + 1] : 0.f;
        float v10 = (p < 12) ? W_pos[p * 64 + k1] : 0.f;
        float v11 = (p < 12) ? W_pos[p * 64 + k1 + 1] : 0.f;
        unsigned H0, L0, H1, L1;
        stage_pair(v00, v01, H0, L0);
        stage_pair(v10, v11, H1, L1);
        pB4[idx] = make_uint4(H0, H1, L0, L1);
    }
    // Wse: frag = nt (0..1); e = nt*8+g; K=16 (valid k<12)
    for (int idx = tid; idx < 2 * 32; idx += TPB) {
        int frag = idx >> 5, lane = idx & 31;
        int gg = lane >> 2, qq = lane & 3;
        int e = frag * 8 + gg;
        int k0 = 2 * qq, k1 = k0 + 8;
        float v00 = (k0 < 12) ? W_se[e * 12 + k0] : 0.f;
        float v01 = (k0 + 1 < 12) ? W_se[e * 12 + k0 + 1] : 0.f;
        float v10 = (k1 < 12) ? W_se[e * 12 + k1] : 0.f;
        float v11 = (k1 + 1 < 12) ? W_se[e * 12 + k1 + 1] : 0.f;
        unsigned H0, L0, H1, L1;
        stage_pair(v00, v01, H0, L0);
        stage_pair(v10, v11, H1, L1);
        sB4[idx] = make_uint4(H0, H1, L0, L1);
    }
    // Wconf: frag = ch (0..3); m = g (valid < 6)
    for (int idx = tid; idx < 4 * 32; idx += TPB) {
        int frag = idx >> 5, lane = idx & 31;
        int gg = lane >> 2, qq = lane & 3;
        int k0 = frag * 16 + 2 * qq, k1 = k0 + 8;
        float v00 = (gg < 6) ? W_conf[gg * 64 + k0] : 0.f;
        float v01 = (gg < 6) ? W_conf[gg * 64 + k0 + 1] : 0.f;
        float v10 = (gg < 6) ? W_conf[gg * 64 + k1] : 0.f;
        float v11 = (gg < 6) ? W_conf[gg * 64 + k1 + 1] : 0.f;
        unsigned H0, L0, H1, L1;
        stage_pair(v00, v01, H0, L0);
        stage_pair(v10, v11, H1, L1);
        cB4[idx] = make_uint4(H0, H1, L0, L1);
    }
    if (tid < 256) smf[OFF_BG + tid] = b_ih[tid] + b_hh[tid];
    if (tid < 16)  smf[OFF_BP + tid] = (tid < 12) ? b_pos[tid] : 0.f;
    if (tid < 16)  smf[OFF_BS + tid] = b_se[tid];
    if (tid < 8)   smf[OFF_BC + tid] = (tid < 6) ? b_conf[tid] : 0.f;

    const int l = tid & 31, g = l >> 2, q = l & 3;
    const int ag0 = blockIdx.x * AB + (tid >> 5) * 32;
    // tile tt rows: ag0 + tt*16 + g  and  ag0 + tt*16 + g + 8
    int rga[2], rgb[2];
    rga[0] = ag0 + g;      rgb[0] = ag0 + g + 8;
    rga[1] = ag0 + 16 + g; rgb[1] = ag0 + 16 + g + 8;

    float* cs = smf + OFF_CS + tid * CST;              // 64 c-values
    uint4* hn4 = (uint4*)(smu + OFF_HN + tid * HNST);  // 16 lane-private h_new slots

    // ---- c state into SMEM (D layout) ----
    #pragma unroll
    for (int tt = 0; tt < 2; tt++)
        #pragma unroll
        for (int grp = 0; grp < 8; grp++) {
            cs[tt * 32 + grp * 4 + 0] = c0[(size_t)rga[tt] * 64 + grp * 8 + 2 * q];
            cs[tt * 32 + grp * 4 + 1] = c0[(size_t)rga[tt] * 64 + grp * 8 + 2 * q + 1];
            cs[tt * 32 + grp * 4 + 2] = c0[(size_t)rgb[tt] * 64 + grp * 8 + 2 * q];
            cs[tt * 32 + grp * 4 + 3] = c0[(size_t)rgb[tt] * 64 + grp * 8 + 2 * q + 1];
        }
    __syncthreads();

    // ---- register-resident A fragments: [tile][chunk 0..3 = h, 4 = x] ----
    unsigned Ah[2][5][4], Al[2][5][4];
    #pragma unroll
    for (int tt = 0; tt < 2; tt++) {
        const float* hg  = h0 + (size_t)rga[tt] * 64;
        const float* hg8 = h0 + (size_t)rgb[tt] * 64;
        #pragma unroll
        for (int ch = 0; ch < 4; ch++) {
            float2 v;
            v = *(const float2*)(hg  + ch * 16 + 2 * q);     stage_pair(v.x, v.y, Ah[tt][ch][0], Al[tt][ch][0]);
            v = *(const float2*)(hg8 + ch * 16 + 2 * q);     stage_pair(v.x, v.y, Ah[tt][ch][1], Al[tt][ch][1]);
            v = *(const float2*)(hg  + ch * 16 + 8 + 2 * q); stage_pair(v.x, v.y, Ah[tt][ch][2], Al[tt][ch][2]);
            v = *(const float2*)(hg8 + ch * 16 + 8 + 2 * q); stage_pair(v.x, v.y, Ah[tt][ch][3], Al[tt][ch][3]);
        }
        float xa[2][4];
        #pragma unroll
        for (int rr = 0; rr < 2; rr++) {
            int agent = rr ? rgb[tt] : rga[tt];
            float rx = traj_rel[2 * agent], ry = traj_rel[2 * agent + 1];
            #pragma unroll
            for (int u = 0; u < 4; u++) {
                int e = (u < 2) ? (2 * q + u) : (8 + 2 * q + (u - 2));
                float se = 0.f, so = 0.f;
                #pragma unroll
                for (int p = 0; p < 6; p++) { se += W_se[e * 12 + 2 * p]; so += W_se[e * 12 + 2 * p + 1]; }
                float s = b_se[e] + rx * se + ry * so;
                xa[rr][u] = s > 0.f ? s : 0.01f * s;
            }
        }
        stage_pair(xa[0][0], xa[0][1], Ah[tt][4][0], Al[tt][4][0]);
        stage_pair(xa[1][0], xa[1][1], Ah[tt][4][1], Al[tt][4][1]);
        stage_pair(xa[0][2], xa[0][3], Ah[tt][4][2], Al[tt][4][2]);
        stage_pair(xa[1][2], xa[1][3], Ah[tt][4][3], Al[tt][4][3]);
    }

    float* outA0 = out + (size_t)rga[0] * 360;
    float* outB0 = out + (size_t)rgb[0] * 360;
    float* outA1 = out + (size_t)rga[1] * 360;
    float* outB1 = out + (size_t)rgb[1] * 360;

    #pragma unroll 1
    for (int t = 0; t < T; t++) {
        // ---- gates: 8 groups; each B frag load feeds BOTH tiles ----
        #pragma unroll 1
        for (int grp = 0; grp < 8; grp++) {
            float acc[2][4][4];
            #pragma unroll
            for (int gate = 0; gate < 4; gate++) {
                float2 bb = *(const float2*)(smf + OFF_BG + gate * 64 + grp * 8 + 2 * q);
                #pragma unroll
                for (int tt = 0; tt < 2; tt++) {
                    acc[tt][gate][0] = bb.x; acc[tt][gate][1] = bb.y;
                    acc[tt][gate][2] = bb.x; acc[tt][gate][3] = bb.y;
                }
            }
            #pragma unroll
            for (int ch = 0; ch < 5; ch++) {
                #pragma unroll
                for (int gate = 0; gate < 4; gate++) {
                    uint4 B = gB4[(ch * 32 + gate * 8 + grp) * 32 + l];
                    #pragma unroll
                    for (int tt = 0; tt < 2; tt++) {
                        mmab(acc[tt][gate], Ah[tt][ch], B.x, B.y);
                        mmab(acc[tt][gate], Al[tt][ch], B.x, B.y);
                        mmab(acc[tt][gate], Ah[tt][ch], B.z, B.w);
                    }
                }
            }
            #pragma unroll
            for (int tt = 0; tt < 2; tt++) {
                float hv[4];
                #pragma unroll
                for (int j = 0; j < 4; j++) {
                    float cc = fsig(acc[tt][1][j]) * cs[tt * 32 + grp * 4 + j]
                             + fsig(acc[tt][0][j]) * tanh_(acc[tt][2][j]);
                    cs[tt * 32 + grp * 4 + j] = cc;
                    hv[j] = fsig(acc[tt][3][j]) * tanh_(cc);
                }
                unsigned H0, L0, H1, L1;
                stage_pair(hv[0], hv[1], H0, L0);
                stage_pair(hv[2], hv[3], H1, L1);
                hn4[tt * 8 + grp] = make_uint4(H0, H1, L0, L1);   // lane-private
            }
        }
        // commit h_new -> A chunks 0..3 (lane-local SMEM reload, no sync)
        #pragma unroll
        for (int tt = 0; tt < 2; tt++)
            #pragma unroll
            for (int ch = 0; ch < 4; ch++) {
                uint4 a = hn4[tt * 8 + 2 * ch], b = hn4[tt * 8 + 2 * ch + 1];
                Ah[tt][ch][0] = a.x; Ah[tt][ch][1] = a.y; Ah[tt][ch][2] = b.x; Ah[tt][ch][3] = b.y;
                Al[tt][ch][0] = a.z; Al[tt][ch][1] = a.w; Al[tt][ch][2] = b.z; Al[tt][ch][3] = b.w;
            }

        // ---- rel = h_new @ Wpos^T + bpos ----
        float ar[2][2][4];
        {
            float2 b0 = *(const float2*)(smf + OFF_BP + 2 * q);
            float2 b1 = *(const float2*)(smf + OFF_BP + 8 + 2 * q);
            #pragma unroll
            for (int tt = 0; tt < 2; tt++) {
                ar[tt][0][0] = b0.x; ar[tt][0][1] = b0.y; ar[tt][0][2] = b0.x; ar[tt][0][3] = b0.y;
                ar[tt][1][0] = b1.x; ar[tt][1][1] = b1.y; ar[tt][1][2] = b1.x; ar[tt][1][3] = b1.y;
            }
        }
        #pragma unroll
        for (int ch = 0; ch < 4; ch++) {
            #pragma unroll
            for (int nt = 0; nt < 2; nt++) {
                uint4 B = pB4[(ch * 2 + nt) * 32 + l];
                #pragma unroll
                for (int tt = 0; tt < 2; tt++) {
                    mmab(ar[tt][nt], Ah[tt][ch], B.x, B.y);
                    mmab(ar[tt][nt], Al[tt][ch], B.x, B.y);
                    mmab(ar[tt][nt], Ah[tt][ch], B.z, B.w);
                }
            }
        }
        *(float2*)(outA0 + q * 60 + t * 2) = make_float2(ar[0][0][0], ar[0][0][1]);
        *(float2*)(outB0 + q * 60 + t * 2) = make_float2(ar[0][0][2], ar[0][0][3]);
        *(float2*)(outA1 + q * 60 + t * 2) = make_float2(ar[1][0][0], ar[1][0][1]);
        *(float2*)(outB1 + q * 60 + t * 2) = make_float2(ar[1][0][2], ar[1][0][3]);
        if (q < 2) {
            *(float2*)(outA0 + (4 + q) * 60 + t * 2) = make_float2(ar[0][1][0], ar[0][1][1]);
            *(float2*)(outB0 + (4 + q) * 60 + t * 2) = make_float2(ar[0][1][2], ar[0][1][3]);
            *(float2*)(outA1 + (4 + q) * 60 + t * 2) = make_float2(ar[1][1][0], ar[1][1][1]);
            *(float2*)(outB1 + (4 + q) * 60 + t * 2) = make_float2(ar[1][1][2], ar[1][1][3]);
        }
        // rel as A fragments (B rows >= 12 staged as 0)
        unsigned rH[2][4], rL[2][4];
        #pragma unroll
        for (int tt = 0; tt < 2; tt++) {
            stage_pair(ar[tt][0][0], ar[tt][0][1], rH[tt][0], rL[tt][0]);
            stage_pair(ar[tt][0][2], ar[tt][0][3], rH[tt][1], rL[tt][1]);
            stage_pair(ar[tt][1][0], ar[tt][1][1], rH[tt][2], rL[tt][2]);
            stage_pair(ar[tt][1][2], ar[tt][1][3], rH[tt][3], rL[tt][3]);
        }

        // ---- x = lrelu(rel @ Wse^T + bse) -> A chunk 4 ----
        float ax[2][2][4];
        {
            float2 b0 = *(const float2*)(smf + OFF_BS + 2 * q);
            float2 b1 = *(const float2*)(smf + OFF_BS + 8 + 2 * q);
            #pragma unroll
            for (int tt = 0; tt < 2; tt++) {
                ax[tt][0][0] = b0.x; ax[tt][0][1] = b0.y; ax[tt][0][2] = b0.x; ax[tt][0][3] = b0.y;
                ax[tt][1][0] = b1.x; ax[tt][1][1] = b1.y; ax[tt][1][2] = b1.x; ax[tt][1][3] = b1.y;
            }
        }
        #pragma unroll
        for (int nt = 0; nt < 2; nt++) {
            uint4 B = sB4[nt * 32 + l];
            #pragma unroll
            for (int tt = 0; tt < 2; tt++) {
                mmab(ax[tt][nt], rH[tt], B.x, B.y);
                mmab(ax[tt][nt], rL[tt], B.x, B.y);
                mmab(ax[tt][nt], rH[tt], B.z, B.w);
            }
        }
        #pragma unroll
        for (int tt = 0; tt < 2; tt++) {
            #pragma unroll
            for (int nt = 0; nt < 2; nt++)
                #pragma unroll
                for (int j = 0; j < 4; j++)
                    ax[tt][nt][j] = ax[tt][nt][j] > 0.f ? ax[tt][nt][j] : 0.01f * ax[tt][nt][j];
            stage_pair(ax[tt][0][0], ax[tt][0][1], Ah[tt][4][0], Al[tt][4][0]);
            stage_pair(ax[tt][0][2], ax[tt][0][3], Ah[tt][4][1], Al[tt][4][1]);
            stage_pair(ax[tt][1][0], ax[tt][1][1], Ah[tt][4][2], Al[tt][4][2]);
            stage_pair(ax[tt][1][2], ax[tt][1][3], Ah[tt][4][3], Al[tt][4][3]);
        }
    }

    // ---- confidence head: softmax(h @ Wconf^T + bconf) per tile ----
    #pragma unroll
    for (int tt = 0; tt < 2; tt++) {
        float ac[4];
        {
            float2 bc = *(const float2*)(smf + OFF_BC + 2 * q);
            ac[0] = bc.x; ac[1] = bc.y; ac[2] = bc.x; ac[3] = bc.y;
        }
        #pragma unroll
        for (int ch = 0; ch < 4; ch++) {
            uint4 B = cB4[ch * 32 + l];
            mmab(ac, Ah[tt][ch], B.x, B.y);
            mmab(ac, Al[tt][ch], B.x, B.y);
            mmab(ac, Ah[tt][ch], B.z, B.w);
        }
        bool v0 = (2 * q) < 6, v1 = (2 * q + 1) < 6;
        float la = fmaxf(v0 ? ac[0] : -1e30f, v1 ? ac[1] : -1e30f);
        float lb = fmaxf(v0 ? ac[2] : -1e30f, v1 ? ac[3] : -1e30f);
        la = fmaxf(la, __shfl_xor_sync(0xffffffffu, la, 1));
        la = fmaxf(la, __shfl_xor_sync(0xffffffffu, la, 2));
        lb = fmaxf(lb, __shfl_xor_sync(0xffffffffu, lb, 1));
        lb = fmaxf(lb, __shfl_xor_sync(0xffffffffu, lb, 2));
        float ea0 = v0 ? __expf(ac[0] - la) : 0.f, ea1 = v1 ? __expf(ac[1] - la) : 0.f;
        float eb0 = v0 ? __expf(ac[2] - lb) : 0.f, eb1 = v1 ? __expf(ac[3] - lb) : 0.f;
        float sa = ea0 + ea1, sb = eb0 + eb1;
        sa += __shfl_xor_sync(0xffffffffu, sa, 1); sa += __shfl_xor_sync(0xffffffffu, sa, 2);
        sb += __shfl_xor_sync(0xffffffffu, sb, 1); sb += __shfl_xor_sync(0xffffffffu, sb, 2);
        float ra = frcp_(sa), rb = frcp_(sb);
        if (q < 3) {
            float* cA = out + CONF_BASE + (size_t)rga[tt] * NM + 2 * q;
            float* cB = out + CONF_BASE + (size_t)rgb[tt] * NM + 2 * q;
            *(float2*)cA = make_float2(ea0 * ra, ea1 * ra);
            *(float2*)cB = make_float2(eb0 * rb, eb1 * rb);
        }
    }
}

extern "C" void kernel_launch(void* const* d_in, const int* in_sizes, int n_in,
                              void* d_out, int out_size)
{
    // 0 traj_abs (unused), 1 traj_rel, 2 h0, 3 c0, 4 W_ih, 5 W_hh,
    // 6 b_ih, 7 b_hh, 8 W_se, 9 b_se, 10 W_pos, 11 b_pos, 12 W_conf, 13 b_conf
    const float* traj_rel = (const float*)d_in[1];
    const float* h0       = (const float*)d_in[2];
    const float* c0       = (const float*)d_in[3];
    const float* W_ih     = (const float*)d_in[4];
    const float* W_hh     = (const float*)d_in[5];
    const float* b_ih     = (const float*)d_in[6];
    const float* b_hh     = (const float*)d_in[7];
    const float* W_se     = (const float*)d_in[8];
    const float* b_se     = (const float*)d_in[9];
    const float* W_pos    = (const float*)d_in[10];
    const float* b_pos    = (const float*)d_in[11];
    const float* W_conf   = (const float*)d_in[12];
    const float* b_conf   = (const float*)d_in[13];
    float* out = (float*)d_out;

    (void)cudaFuncSetAttribute(decoder_lstm_kernel,
                               cudaFuncAttributeMaxDynamicSharedMemorySize,
                               SMEM_BYTES);

    decoder_lstm_kernel<<<NBLK, TPB, SMEM_BYTES>>>(
        traj_rel, h0, c0, W_ih, W_hh, b_ih, b_hh,
        W_se, b_se, W_pos, b_pos, W_conf, b_conf, out);
}